// round 3
// baseline (speedup 1.0000x reference)
#include <cuda_runtime.h>

#define SIDE   32
#define UNITS  1024
#define BATCH  128
#define TSTEPS 512
#define NT     128
#define MDW    34   // Md row stride in ulls (32 + 2 pad)

typedef unsigned long long ull;

#define FMA2(acc, a, m)    asm("fma.rn.f32x2 %0, %1, %2, %0;" : "+l"(acc) : "l"(a), "l"(m))
#define FADD2(d, a, b)     asm("add.rn.f32x2 %0, %1, %2;" : "=l"(d) : "l"(a), "l"(b))
#define PACK2(d, lo, hi)   asm("mov.b64 %0, {%1, %2};" : "=l"(d) : "f"(lo), "f"(hi))
#define UNPACK2(lo, hi, s) asm("mov.b64 {%0, %1}, %2;" : "=f"(lo), "=f"(hi) : "l"(s))

__global__ __launch_bounds__(NT, 1)
void minrnn_kernel(const float* __restrict__ x, const float* __restrict__ b,
                   const float* __restrict__ b2, const float* __restrict__ h0,
                   float* __restrict__ out)
{
    // At[buf][j][r] = A[r][j]   (A^T, 128B rows, conflict-free by construction)
    __shared__ __align__(16) float At[2][SIDE][SIDE];
    // Md[buf][j][c] = { M[j][c], M[j][c] }  (duplicated for FFMA2)
    __shared__ __align__(16) ull   Md[2][SIDE][MDW];

    const int tid = threadIdx.x;
    const int bb  = blockIdx.x;
    const int rg  = tid & 7;          // row quad: rows 4rg..4rg+3
    const int cg  = tid >> 3;         // col pair: cols 2cg, 2cg+1
    const int r0  = rg * 4;
    const int c0  = cg * 2;
    const int jf  = tid >> 2;         // M-fill row
    const int cf  = tid & 3;          // M-fill col block (8 cols)

    // b2 packs: b2p[cc][p] = { b2[r0+2p][c0+cc], b2[r0+2p+1][c0+cc] }
    ull b2p[2][2];
#pragma unroll
    for (int cc = 0; cc < 2; cc++)
#pragma unroll
        for (int p = 0; p < 2; p++)
            PACK2(b2p[cc][p], b2[(r0 + 2*p) * SIDE + c0 + cc],
                              b2[(r0 + 2*p + 1) * SIDE + c0 + cc]);

    // bias packs for M fill (units jf*32 + 8cf + {0..7})
    ull bfp[4];
    {
        const float* bp = b + jf * SIDE + cf * 8;
#pragma unroll
        for (int w = 0; w < 4; w++) PACK2(bfp[w], bp[2*w], bp[2*w + 1]);
    }

    // x prefetch ring, depth 4. Thread streams floats [tid*8 .. tid*8+7] per step
    // (note jf*32 + cf*8 == tid*8, so fill mapping is the coalesced stream).
    const float* xbase = x + (size_t)bb * TSTEPS * UNITS + tid * 8;
    ulonglong2 xr[4][2];
#pragma unroll
    for (int s = 0; s < 4; s++) {
        const ulonglong2* p = (const ulonglong2*)(xbase + s * UNITS);
        xr[s][0] = p[0]; xr[s][1] = p[1];
    }

    // ---- prologue: buffer 0 = { A(0) = h0 + b2 ; M(0) = b + x(0) } ----
    {
        const float* hp = h0 + bb * UNITS;
#pragma unroll
        for (int cc = 0; cc < 2; cc++) {
            ull v0, v1, hk;
            PACK2(hk, hp[r0 * SIDE + c0 + cc], hp[(r0 + 1) * SIDE + c0 + cc]);
            FADD2(v0, hk, b2p[cc][0]);
            PACK2(hk, hp[(r0 + 2) * SIDE + c0 + cc], hp[(r0 + 3) * SIDE + c0 + cc]);
            FADD2(v1, hk, b2p[cc][1]);
            ulonglong2 st; st.x = v0; st.y = v1;
            *(ulonglong2*)&At[0][c0 + cc][r0] = st;
        }
        ull xs[4] = { xr[0][0].x, xr[0][0].y, xr[0][1].x, xr[0][1].y };
        ull* dst = &Md[0][jf][cf * 8];
#pragma unroll
        for (int w = 0; w < 4; w++) {
            ull m, d0, d1; float f0, f1;
            FADD2(m, xs[w], bfp[w]);
            UNPACK2(f0, f1, m);
            PACK2(d0, f0, f0); PACK2(d1, f1, f1);
            ulonglong2 st; st.x = d0; st.y = d1;
            *(ulonglong2*)(dst + 2*w) = st;
        }
    }
    __syncthreads();

    ull acc00 = 0, acc01 = 0, acc10 = 0, acc11 = 0;

#pragma unroll 2
    for (int t = 0; t < TSTEPS; t++) {
        const int pb = t & 1;
        const int nb = pb ^ 1;

        // prefetch x(t+4) into freed ring slot
        if (t + 4 < TSTEPS) {
            const ulonglong2* p = (const ulonglong2*)(xbase + (size_t)(t + 4) * UNITS);
            xr[t & 3][0] = p[0]; xr[t & 3][1] = p[1];
        }

        // out[r0..r0+3][c0..c0+1] = sum_j A[r][j] * M[j][c]
        const float* Aj = &At[pb][0][r0];
        const ull*   Mj = &Md[pb][0][c0];
        ull n00 = 0, n01 = 0, n10 = 0, n11 = 0;
#pragma unroll
        for (int j = 0; j < SIDE; j++) {
            ulonglong2 a = *(const ulonglong2*)(Aj + j * SIDE);   // {A[r0],A[r0+1]},{A[r0+2],A[r0+3]}
            ulonglong2 m = *(const ulonglong2*)(Mj + j * MDW);    // {M[j][c0]}dup, {M[j][c0+1]}dup
            FMA2(n00, a.x, m.x);
            FMA2(n01, a.x, m.y);
            FMA2(n10, a.y, m.x);
            FMA2(n11, a.y, m.y);
        }
        acc00 = n00; acc01 = n01; acc10 = n10; acc11 = n11;

        if (t + 1 < TSTEPS) {
            // A(t+1) = out + b2  -> At[nb]
            ull v0, v1;
            FADD2(v0, acc00, b2p[0][0]); FADD2(v1, acc10, b2p[0][1]);
            { ulonglong2 st; st.x = v0; st.y = v1; *(ulonglong2*)&At[nb][c0][r0] = st; }
            FADD2(v0, acc01, b2p[1][0]); FADD2(v1, acc11, b2p[1][1]);
            { ulonglong2 st; st.x = v0; st.y = v1; *(ulonglong2*)&At[nb][c0 + 1][r0] = st; }

            // M(t+1) = b + x(t+1) -> Md[nb] (duplicated)
            const int s = (t + 1) & 3;
            ull xs[4] = { xr[s][0].x, xr[s][0].y, xr[s][1].x, xr[s][1].y };
            ull* dst = &Md[nb][jf][cf * 8];
#pragma unroll
            for (int w = 0; w < 4; w++) {
                ull m, d0, d1; float f0, f1;
                FADD2(m, xs[w], bfp[w]);
                UNPACK2(f0, f1, m);
                PACK2(d0, f0, f0); PACK2(d1, f1, f1);
                ulonglong2 st; st.x = d0; st.y = d1;
                *(ulonglong2*)(dst + 2*w) = st;
            }
            __syncthreads();
        }
    }

    // final h (without b2): acc00={o[r0][c0],o[r0+1][c0]}, acc01={o[r0][c0+1],o[r0+1][c0+1]}, ...
    {
        float a0l, a0h, a1l, a1h, b0l, b0h, b1l, b1h;
        UNPACK2(a0l, a0h, acc00); UNPACK2(a1l, a1h, acc01);
        UNPACK2(b0l, b0h, acc10); UNPACK2(b1l, b1h, acc11);
        float* op = out + bb * UNITS + r0 * SIDE + c0;
        *(float2*)(op + 0 * SIDE) = make_float2(a0l, a1l);
        *(float2*)(op + 1 * SIDE) = make_float2(a0h, a1h);
        *(float2*)(op + 2 * SIDE) = make_float2(b0l, b1l);
        *(float2*)(op + 3 * SIDE) = make_float2(b0h, b1h);
    }
}

extern "C" void kernel_launch(void* const* d_in, const int* in_sizes, int n_in,
                              void* d_out, int out_size)
{
    const float* x  = (const float*)d_in[0];   // [128, 512, 1024]
    const float* b  = (const float*)d_in[1];   // [1024]
    const float* b2 = (const float*)d_in[2];   // [1024]
    const float* h0 = (const float*)d_in[3];   // [128, 1024]
    float* out = (float*)d_out;                // [128, 1024]
    minrnn_kernel<<<BATCH, NT>>>(x, b, b2, h0, out);
}

// round 4
// speedup vs baseline: 1.6117x; 1.6117x over previous
#include <cuda_runtime.h>

#define SIDE   32
#define UNITS  1024
#define BATCH  128
#define TSTEPS 512
#define NT     128
#define MDW    34   // Md row stride in ulls (32 + 2 pad) -> 272B rows
#define PSW    10   // Psh row stride in ulls (8 + 2 pad) -> 80B rows

typedef unsigned long long ull;

#define FMA2(acc, a, m)    asm("fma.rn.f32x2 %0, %1, %2, %0;" : "+l"(acc) : "l"(a), "l"(m))
#define FADD2(d, a, b)     asm("add.rn.f32x2 %0, %1, %2;" : "=l"(d) : "l"(a), "l"(b))
#define PACK2(d, lo, hi)   asm("mov.b64 %0, {%1, %2};" : "=l"(d) : "f"(lo), "f"(hi))
#define UNPACK2(lo, hi, s) asm("mov.b64 {%0, %1}, %2;" : "=f"(lo), "=f"(hi) : "l"(s))

__global__ __launch_bounds__(NT, 1)
void minrnn_kernel(const float* __restrict__ x, const float* __restrict__ b,
                   const float* __restrict__ b2, const float* __restrict__ h0,
                   float* __restrict__ out)
{
    // At[buf][j][r] = A[r][j]  (A^T, 128B rows, conflict-free)
    __shared__ __align__(16) float At[2][SIDE][SIDE];
    // Md[buf][j][c] = {M[j][c], M[j][c]} duplicated for FFMA2
    __shared__ __align__(16) ull   Md[2][SIDE][MDW];
    // partial-sum exchange (jh=1 -> jh=0)
    __shared__ __align__(16) ull   Psh[64][PSW];

    const int tid = threadIdx.x;
    const int bb  = blockIdx.x;
    const int pos = tid & 63;        // tile position
    const int jh  = tid >> 6;        // j-half: 0 -> j 0..15, 1 -> j 16..31
    const int rg  = pos & 7;         // row quad
    const int cg  = pos >> 3;        // col quad
    const int r0  = rg * 4;
    const int c0  = cg * 4;
    const int jb  = jh * 16;

    // ---- jh=0 constants: b2 packs b2p[p][cc] = {b2[r0+2p][c0+cc], b2[r0+2p+1][c0+cc]} ----
    ull b2p[2][4];
    if (jh == 0) {
#pragma unroll
        for (int p = 0; p < 2; p++)
#pragma unroll
            for (int cc = 0; cc < 4; cc++)
                PACK2(b2p[p][cc], b2[(r0 + 2*p) * SIDE + c0 + cc],
                                  b2[(r0 + 2*p + 1) * SIDE + c0 + cc]);
    }

    // ---- jh=1 constants: M-fill role (16 M entries: row jm, cols cb..cb+15) ----
    const int jm = pos >> 1;
    const int cb = (pos & 1) * 16;
    ull bfp[8];
    const float* xbase = x + (size_t)bb * TSTEPS * UNITS + pos * 16;
    float4 xr[2][4];                 // x prefetch ring, depth 2
    if (jh == 1) {
        const float* bp = b + jm * SIDE + cb;
#pragma unroll
        for (int e = 0; e < 8; e++) PACK2(bfp[e], bp[2*e], bp[2*e + 1]);
#pragma unroll
        for (int s = 0; s < 2; s++)
#pragma unroll
            for (int q = 0; q < 4; q++)
                xr[s][q] = *(const float4*)(xbase + (size_t)s * UNITS + q * 4);
    }

    // ---- prologue: buffer 0 ----
    if (jh == 0) {
        // At[0] = (h0 + b2)^T for this thread's 4x4 tile
        const float* hp = h0 + bb * UNITS;
#pragma unroll
        for (int cc = 0; cc < 4; cc++) {
            ull hk, v0, v1;
            PACK2(hk, hp[r0 * SIDE + c0 + cc], hp[(r0 + 1) * SIDE + c0 + cc]);
            FADD2(v0, hk, b2p[0][cc]);
            PACK2(hk, hp[(r0 + 2) * SIDE + c0 + cc], hp[(r0 + 3) * SIDE + c0 + cc]);
            FADD2(v1, hk, b2p[1][cc]);
            ulonglong2 st; st.x = v0; st.y = v1;
            *(ulonglong2*)&At[0][c0 + cc][r0] = st;
        }
    } else {
        // Md[0] = dup(b + x(0))
#pragma unroll
        for (int q = 0; q < 4; q++) {
            float4 v = xr[0][q];
            ull xp0, xp1, m0, m1, d0, d1, d2, d3;
            float f0, f1, f2, f3;
            PACK2(xp0, v.x, v.y); PACK2(xp1, v.z, v.w);
            FADD2(m0, xp0, bfp[2*q]); FADD2(m1, xp1, bfp[2*q + 1]);
            UNPACK2(f0, f1, m0); UNPACK2(f2, f3, m1);
            PACK2(d0, f0, f0); PACK2(d1, f1, f1);
            PACK2(d2, f2, f2); PACK2(d3, f3, f3);
            ulonglong2 s0; s0.x = d0; s0.y = d1;
            ulonglong2 s1; s1.x = d2; s1.y = d3;
            *(ulonglong2*)&Md[0][jm][cb + 4*q]     = s0;
            *(ulonglong2*)&Md[0][jm][cb + 4*q + 2] = s1;
        }
    }
    __syncthreads();

#pragma unroll 2
    for (int t = 0; t < TSTEPS; t++) {
        const int pb = t & 1;
        const int nb = pb ^ 1;

        // jh=1: prefetch x(t+2) into freed ring slot (issued ~1.8 steps ahead of use)
        if (jh == 1 && t + 2 < TSTEPS) {
#pragma unroll
            for (int q = 0; q < 4; q++)
                xr[t & 1][q] = *(const float4*)(xbase + (size_t)(t + 2) * UNITS + q * 4);
        }

        // ---- j-loop: 16 js, 3-stage modulo software pipeline ----
        ull acc[2][4];
#pragma unroll
        for (int p = 0; p < 2; p++)
#pragma unroll
            for (int cc = 0; cc < 4; cc++) acc[p][cc] = 0;

        ulonglong2 sa[3], sm0[3], sm1[3];
#pragma unroll
        for (int s = 0; s < 2; s++) {
            sa[s]  = *(const ulonglong2*)&At[pb][jb + s][r0];
            sm0[s] = *(const ulonglong2*)&Md[pb][jb + s][c0];
            sm1[s] = *(const ulonglong2*)&Md[pb][jb + s][c0 + 2];
        }
#pragma unroll
        for (int jj = 0; jj < 16; jj++) {
            if (jj + 2 < 16) {                // load group jj+2 BEFORE consuming jj
                const int s = (jj + 2) % 3;
                sa[s]  = *(const ulonglong2*)&At[pb][jb + jj + 2][r0];
                sm0[s] = *(const ulonglong2*)&Md[pb][jb + jj + 2][c0];
                sm1[s] = *(const ulonglong2*)&Md[pb][jb + jj + 2][c0 + 2];
            }
            const int s = jj % 3;
            FMA2(acc[0][0], sa[s].x, sm0[s].x);
            FMA2(acc[1][0], sa[s].y, sm0[s].x);
            FMA2(acc[0][1], sa[s].x, sm0[s].y);
            FMA2(acc[1][1], sa[s].y, sm0[s].y);
            FMA2(acc[0][2], sa[s].x, sm1[s].x);
            FMA2(acc[1][2], sa[s].y, sm1[s].x);
            FMA2(acc[0][3], sa[s].x, sm1[s].y);
            FMA2(acc[1][3], sa[s].y, sm1[s].y);
        }

        // jh=1: publish partials right away (read after bar0 by jh=0)
        if (jh == 1) {
#pragma unroll
            for (int p = 0; p < 2; p++) {
#pragma unroll
                for (int cc = 0; cc < 4; cc += 2) {
                    ulonglong2 st; st.x = acc[p][cc]; st.y = acc[p][cc + 1];
                    *(ulonglong2*)&Psh[pos][p * 4 + cc] = st;
                }
            }
        }
        __syncthreads();   // bar0: j-loop reads of buf pb done; partials visible

        if (jh == 0) {
            // reduce partner partials
#pragma unroll
            for (int p = 0; p < 2; p++) {
#pragma unroll
                for (int cc = 0; cc < 4; cc += 2) {
                    ulonglong2 pr = *(const ulonglong2*)&Psh[pos][p * 4 + cc];
                    FADD2(acc[p][cc],     acc[p][cc],     pr.x);
                    FADD2(acc[p][cc + 1], acc[p][cc + 1], pr.y);
                }
            }
            if (t + 1 < TSTEPS) {
                // A(t+1) = h + b2 -> At[nb]
#pragma unroll
                for (int cc = 0; cc < 4; cc++) {
                    ull v0, v1;
                    FADD2(v0, acc[0][cc], b2p[0][cc]);
                    FADD2(v1, acc[1][cc], b2p[1][cc]);
                    ulonglong2 st; st.x = v0; st.y = v1;
                    *(ulonglong2*)&At[nb][c0 + cc][r0] = st;
                }
            } else {
                // final h (without b2) -> GMEM, one float4 per row
                float lo[4], hi[4];
                float* op = out + bb * UNITS;
#pragma unroll
                for (int p = 0; p < 2; p++) {
#pragma unroll
                    for (int cc = 0; cc < 4; cc++) UNPACK2(lo[cc], hi[cc], acc[p][cc]);
                    *(float4*)(op + (r0 + 2*p)     * SIDE + c0) = make_float4(lo[0], lo[1], lo[2], lo[3]);
                    *(float4*)(op + (r0 + 2*p + 1) * SIDE + c0) = make_float4(hi[0], hi[1], hi[2], hi[3]);
                }
            }
        } else if (t + 1 < TSTEPS) {
            // M(t+1) = dup(b + x(t+1)) -> Md[nb]
            const int s = (t + 1) & 1;
#pragma unroll
            for (int q = 0; q < 4; q++) {
                float4 v = xr[s][q];
                ull xp0, xp1, m0, m1, d0, d1, d2, d3;
                float f0, f1, f2, f3;
                PACK2(xp0, v.x, v.y); PACK2(xp1, v.z, v.w);
                FADD2(m0, xp0, bfp[2*q]); FADD2(m1, xp1, bfp[2*q + 1]);
                UNPACK2(f0, f1, m0); UNPACK2(f2, f3, m1);
                PACK2(d0, f0, f0); PACK2(d1, f1, f1);
                PACK2(d2, f2, f2); PACK2(d3, f3, f3);
                ulonglong2 s0; s0.x = d0; s0.y = d1;
                ulonglong2 s1; s1.x = d2; s1.y = d3;
                *(ulonglong2*)&Md[nb][jm][cb + 4*q]     = s0;
                *(ulonglong2*)&Md[nb][jm][cb + 4*q + 2] = s1;
            }
        }
        __syncthreads();   // bar1: buf nb complete before next step's j-loop
    }
}

extern "C" void kernel_launch(void* const* d_in, const int* in_sizes, int n_in,
                              void* d_out, int out_size)
{
    const float* x  = (const float*)d_in[0];   // [128, 512, 1024]
    const float* b  = (const float*)d_in[1];   // [1024]
    const float* b2 = (const float*)d_in[2];   // [1024]
    const float* h0 = (const float*)d_in[3];   // [128, 1024]
    float* out = (float*)d_out;                // [128, 1024]
    minrnn_kernel<<<BATCH, NT>>>(x, b, b2, h0, out);
}